// round 4
// baseline (speedup 1.0000x reference)
#include <cuda_runtime.h>
#include <math.h>
#include <stdint.h>

#define N_BATCH 4096
#define V_N     26
#define C_N     256
#define K_N     3
#define NV      (N_BATCH * V_N)            /* 106496 */
#define TS      25

/* ------------------------------------------------------------------ */
/* Device scratch (no cudaMalloc allowed)                              */
/* ------------------------------------------------------------------ */
__device__ float g_HA[(size_t)NV * C_N];        /* hidden ping  [NV,256] */
__device__ float g_HB[(size_t)NV * C_N];        /* hidden pong  */
__device__ float g_Y [(size_t)NV * 3 * C_N];    /* conv out     [NV,768] */
__device__ float g_M [(size_t)NV * C_N];        /* msg          [NV,256] */
__device__ float g_G [(size_t)NV * 3 * C_N];    /* m@[Whr|Whi|Whh]^T     */
__device__ float g_D1[(size_t)NV * C_N];
__device__ float g_D2[(size_t)NV * C_N];
__device__ float g_P [4][(size_t)NV * 3];       /* pred history ring     */
__device__ float g_Whcat[3 * C_N * C_N];
__device__ __align__(16) float g_Aadj[K_N * V_N * 28];  /* padded 26->28 */

/* ------------------------------------------------------------------ */
/* JAX threefry2x32 noise replication (partitionable path, modern      */
/* default jax_threefry_partitionable=True):                           */
/*   per element i: (o0,o1) = threefry2x32(key=(0,1), x0=hi(i)=0,      */
/*                                          x1=lo(i)=i)                */
/*   bits = o0 ^ o1              <-- 32-bit combine is XOR of lanes    */
/*   f = bitcast(bits>>9 | 0x3f800000) - 1; u = max(lo, f*2 + lo)      */
/*   noise = 5e-4 * sqrt(2) * erfinv(u)                                */
/* ------------------------------------------------------------------ */
__device__ __forceinline__ uint32_t rotl32(uint32_t x, uint32_t r) {
    return (x << r) | (x >> (32u - r));
}

__device__ __forceinline__ float jax_noise(int s, int r, int d)
{
    uint32_t idx = (uint32_t)((s * NV + r) * 3 + d);
    uint32_t x0 = 0u;          /* high 32 bits of flat index (always 0) */
    uint32_t x1 = idx;         /* low 32 bits                           */
    const uint32_t K0 = 0u, K1 = 1u, K2 = 0x1BD11BDBu; /* 0^1^0x1BD11BDA */
    x0 += K0; x1 += K1;
#define QR(rv) { x0 += x1; x1 = rotl32(x1, rv); x1 ^= x0; }
    QR(13) QR(15) QR(26) QR(6)
    x0 += K1; x1 += K2 + 1u;
    QR(17) QR(29) QR(16) QR(24)
    x0 += K2; x1 += K0 + 2u;
    QR(13) QR(15) QR(26) QR(6)
    x0 += K0; x1 += K1 + 3u;
    QR(17) QR(29) QR(16) QR(24)
    x0 += K1; x1 += K2 + 4u;
    QR(13) QR(15) QR(26) QR(6)
    x0 += K2; x1 += K0 + 5u;
#undef QR
    uint32_t bits = x0 ^ x1;                     /* XOR lane combine */
    float f = __uint_as_float((bits >> 9) | 0x3f800000u) - 1.0f;
    const float lo = -0.99999994f;               /* nextafter(-1,0) */
    float u = f * 2.0f + lo;                     /* (1 - lo) rounds to 2.0f */
    u = fmaxf(lo, u);
    return (1.41421354f * erfinvf(u)) * 5e-4f;
}

/* ------------------------------------------------------------------ */
/* SGEMM: C[M,Nout] = A[M,256] @ B[Nout,256]^T  (+bias, +leaky)        */
/* BM=BN=128, BK=8, 256 threads, 8x8 micro-tile. M,Nout multiples of   */
/* 128 and K=256 by construction -> no bounds checks.                  */
/* epi: 0 = none, 1 = +bias, 2 = +bias then leaky_relu(0.1)            */
/* ------------------------------------------------------------------ */
__global__ void __launch_bounds__(256, 2)
sgemm_nt_128(const float* __restrict__ A, const float* __restrict__ B,
             float* __restrict__ C, int Nout,
             const float* __restrict__ bias, int epi)
{
    __shared__ float As[8][128];
    __shared__ float Bs[8][128];
    const int tid = threadIdx.x;
    const int lr  = tid >> 1;          /* 0..127 */
    const int lk  = (tid & 1) << 2;    /* 0 or 4 */
    const float* Ag = A + ((size_t)blockIdx.y * 128 + lr) * 256 + lk;
    const float* Bg = B + ((size_t)blockIdx.x * 128 + lr) * 256 + lk;
    const int tm = (tid >> 4) << 3;
    const int tn = (tid & 15) << 3;

    float acc[8][8];
#pragma unroll
    for (int i = 0; i < 8; i++)
#pragma unroll
        for (int j = 0; j < 8; j++) acc[i][j] = 0.f;

    for (int k0 = 0; k0 < 256; k0 += 8) {
        float4 av = *(const float4*)(Ag + k0);
        float4 bv = *(const float4*)(Bg + k0);
        __syncthreads();
        As[lk + 0][lr] = av.x; As[lk + 1][lr] = av.y;
        As[lk + 2][lr] = av.z; As[lk + 3][lr] = av.w;
        Bs[lk + 0][lr] = bv.x; Bs[lk + 1][lr] = bv.y;
        Bs[lk + 2][lr] = bv.z; Bs[lk + 3][lr] = bv.w;
        __syncthreads();
#pragma unroll
        for (int kk = 0; kk < 8; kk++) {
            float4 a0 = *(const float4*)&As[kk][tm];
            float4 a1 = *(const float4*)&As[kk][tm + 4];
            float4 b0 = *(const float4*)&Bs[kk][tn];
            float4 b1 = *(const float4*)&Bs[kk][tn + 4];
            float ar[8] = {a0.x, a0.y, a0.z, a0.w, a1.x, a1.y, a1.z, a1.w};
            float br[8] = {b0.x, b0.y, b0.z, b0.w, b1.x, b1.y, b1.z, b1.w};
#pragma unroll
            for (int i = 0; i < 8; i++)
#pragma unroll
                for (int j = 0; j < 8; j++)
                    acc[i][j] += ar[i] * br[j];
        }
    }

    const int cm = blockIdx.y * 128 + tm;
    const int cn = blockIdx.x * 128 + tn;
    float bb[8];
#pragma unroll
    for (int j = 0; j < 8; j++) bb[j] = bias ? bias[cn + j] : 0.f;
#pragma unroll
    for (int i = 0; i < 8; i++) {
        float* Crow = C + (size_t)(cm + i) * Nout + cn;
#pragma unroll
        for (int j = 0; j < 8; j++) {
            float v = acc[i][j] + bb[j];
            if (epi == 2) v = (v > 0.f) ? v : 0.1f * v;
            Crow[j] = v;
        }
    }
}

/* ------------------------------------------------------------------ */
/* Graph mix: M[(n,w),c] = sum_{k,v} Y[(n,v),k*256+c] * Aadj[k,v,w]    */
/* One block per sample n; Y[n] tile staged in dynamic smem (78 KB).   */
/* ------------------------------------------------------------------ */
__global__ void __launch_bounds__(256)
graphmix_kernel(const float* __restrict__ Y, float* __restrict__ Mout)
{
    extern __shared__ float smY[];                 /* 26*768 floats */
    __shared__ __align__(16) float sA[K_N * V_N * 28];
    const int n = blockIdx.x;
    const int tid = threadIdx.x;
    const float* Yn = Y + (size_t)n * V_N * 768;
    for (int i = tid; i < V_N * 768; i += 256) smY[i] = Yn[i];
    for (int i = tid; i < K_N * V_N * 28; i += 256) sA[i] = g_Aadj[i];
    __syncthreads();

    const int c = tid;
    float acc[28];
#pragma unroll
    for (int w = 0; w < 28; w++) acc[w] = 0.f;

#pragma unroll
    for (int k = 0; k < K_N; k++) {
#pragma unroll
        for (int v = 0; v < V_N; v++) {
            float yv = smY[v * 768 + k * 256 + c];
            const float4* arow = (const float4*)&sA[(k * V_N + v) * 28];
#pragma unroll
            for (int q = 0; q < 7; q++) {
                float4 a4 = arow[q];
                acc[q * 4 + 0] += yv * a4.x;
                acc[q * 4 + 1] += yv * a4.y;
                acc[q * 4 + 2] += yv * a4.z;
                acc[q * 4 + 3] += yv * a4.w;
            }
        }
    }
    float* Mn = Mout + (size_t)n * V_N * 256;
    for (int w = 0; w < V_N; w++) Mn[w * 256 + c] = acc[w];
}

/* ------------------------------------------------------------------ */
/* GRU elementwise: one block per row r=(n,v), thread = channel c      */
/* ------------------------------------------------------------------ */
__global__ void __launch_bounds__(256)
gru_kernel(const float* __restrict__ H, const float* __restrict__ G,
           const float* __restrict__ P1, const float* __restrict__ P2,
           const float* __restrict__ P3,
           const float* __restrict__ Wir, const float* __restrict__ bir,
           const float* __restrict__ Wii, const float* __restrict__ bii,
           const float* __restrict__ Win, const float* __restrict__ bin,
           float* __restrict__ Hnew, int s)
{
    const int r = blockIdx.x;
    const int c = threadIdx.x;
    __shared__ float sx[9];
    if (c < 3) {
        float h1 = P1[r * 3 + c], h2 = P2[r * 3 + c], h3 = P3[r * 3 + c];
        float nz = jax_noise(s, r, c);
        float insv = h2 - h3;
        sx[c]     = h1 + nz;            /* ins_p + noise */
        sx[3 + c] = insv;               /* ins_v          */
        sx[6 + c] = (h1 - h2) - insv;   /* ins_a          */
    }
    __syncthreads();

    float xr = bir[c], xi = bii[c], xn = bin[c];
#pragma unroll
    for (int d = 0; d < 9; d++) {
        float xv = sx[d];
        xr += xv * Wir[c * 9 + d];
        xi += xv * Wii[c * 9 + d];
        xn += xv * Win[c * 9 + d];
    }
    size_t g = (size_t)r * 768;
    float gr = G[g + c], gi = G[g + 256 + c], gh = G[g + 512 + c];
    float rg = 1.f / (1.f + expf(-(xr + gr)));
    float zg = 1.f / (1.f + expf(-(xi + gi)));
    float nn = tanhf(xn + rg * gh);
    float hp = H[(size_t)r * 256 + c];
    Hnew[(size_t)r * 256 + c] = (1.f - zg) * nn + zg * hp;
}

/* ------------------------------------------------------------------ */
/* Output head: res = D2 @ W3^T + b3 ; pred = (h1 + nz) + res          */
/* one warp per row; writes pred history buffer and final output       */
/* ------------------------------------------------------------------ */
__global__ void __launch_bounds__(256)
out_kernel(const float* __restrict__ D2, const float* __restrict__ W3,
           const float* __restrict__ b3, const float* __restrict__ P1,
           float* __restrict__ Pnew, float* __restrict__ out, int s)
{
    const int warp = threadIdx.x >> 5, lane = threadIdx.x & 31;
    const int r = blockIdx.x * 8 + warp;
    const float* row = D2 + (size_t)r * 256;
    float a0 = 0.f, a1 = 0.f, a2 = 0.f;
#pragma unroll
    for (int i = 0; i < 8; i++) {
        int c = lane + 32 * i;
        float v = row[c];
        a0 += v * W3[c];
        a1 += v * W3[256 + c];
        a2 += v * W3[512 + c];
    }
#pragma unroll
    for (int o = 16; o > 0; o >>= 1) {
        a0 += __shfl_down_sync(0xffffffffu, a0, o);
        a1 += __shfl_down_sync(0xffffffffu, a1, o);
        a2 += __shfl_down_sync(0xffffffffu, a2, o);
    }
    if (lane == 0) {
        float res[3] = {a0 + b3[0], a1 + b3[1], a2 + b3[2]};
#pragma unroll
        for (int d = 0; d < 3; d++) {
            float p = (P1[r * 3 + d] + jax_noise(s, r, d)) + res[d];
            Pnew[r * 3 + d] = p;
            out[((size_t)r * TS + s) * 3 + d] = p;
        }
    }
}

/* ------------------------------------------------------------------ */
/* Prep kernels                                                        */
/* ------------------------------------------------------------------ */
__global__ void prep_aadj(const float* __restrict__ A,
                          const float* __restrict__ em,
                          const float* __restrict__ ea)
{
    int i = blockIdx.x * 256 + threadIdx.x;
    if (i >= K_N * V_N * 28) return;
    int w = i % 28, kv = i / 28;
    g_Aadj[i] = (w < V_N) ? (A[kv * V_N + w] * em[kv * V_N + w] + ea[kv * V_N + w])
                          : 0.f;
}

/* hidden [N,C,V] -> H [(n,v),c] via smem transpose, one block per n */
__global__ void __launch_bounds__(256)
transpose_h(const float* __restrict__ hid, float* __restrict__ H)
{
    __shared__ float sm[C_N * V_N];
    const int n = blockIdx.x;
    const float* src = hid + (size_t)n * C_N * V_N;
    for (int i = threadIdx.x; i < C_N * V_N; i += 256) sm[i] = src[i];
    __syncthreads();
    float* dst = H + (size_t)n * V_N * C_N;
    for (int i = threadIdx.x; i < C_N * V_N; i += 256) {
        int v = i >> 8, c = i & 255;
        dst[i] = sm[c * V_N + v];
    }
}

/* ------------------------------------------------------------------ */
/* Host driver (graph-capturable: kernels + D2D async copies only)     */
/* ------------------------------------------------------------------ */
extern "C" void kernel_launch(void* const* d_in, const int* in_sizes, int n_in,
                              void* d_out, int out_size)
{
    const float* in0    = (const float*)d_in[0];
    const float* in1    = (const float*)d_in[1];
    const float* in2    = (const float*)d_in[2];
    const float* hidden = (const float*)d_in[3];
    const float* A      = (const float*)d_in[4];
    const float* emul   = (const float*)d_in[5];
    const float* eadd   = (const float*)d_in[6];
    const float* conv_w = (const float*)d_in[7];
    const float* conv_b = (const float*)d_in[8];
    const float* Wir    = (const float*)d_in[9];
    const float* bir    = (const float*)d_in[10];
    const float* Wii    = (const float*)d_in[11];
    const float* bii    = (const float*)d_in[12];
    const float* Win    = (const float*)d_in[13];
    const float* b_in   = (const float*)d_in[14];
    const float* Whr    = (const float*)d_in[15];
    const float* Whi    = (const float*)d_in[16];
    const float* Whh    = (const float*)d_in[17];
    const float* W1     = (const float*)d_in[18];
    const float* b1     = (const float*)d_in[19];
    const float* W2     = (const float*)d_in[20];
    const float* b2     = (const float*)d_in[21];
    const float* W3     = (const float*)d_in[22];
    const float* b3     = (const float*)d_in[23];
    float* out = (float*)d_out;

    float *pHA, *pHB, *pY, *pM, *pG, *pD1, *pD2, *pWhcat, *pPbase;
    cudaGetSymbolAddress((void**)&pHA,    g_HA);
    cudaGetSymbolAddress((void**)&pHB,    g_HB);
    cudaGetSymbolAddress((void**)&pY,     g_Y);
    cudaGetSymbolAddress((void**)&pM,     g_M);
    cudaGetSymbolAddress((void**)&pG,     g_G);
    cudaGetSymbolAddress((void**)&pD1,    g_D1);
    cudaGetSymbolAddress((void**)&pD2,    g_D2);
    cudaGetSymbolAddress((void**)&pWhcat, g_Whcat);
    cudaGetSymbolAddress((void**)&pPbase, g_P);

    float* Pbuf[4];
    for (int i = 0; i < 4; i++) Pbuf[i] = pPbase + (size_t)i * NV * 3;

    cudaFuncSetAttribute(graphmix_kernel,
                         cudaFuncAttributeMaxDynamicSharedMemorySize,
                         V_N * 768 * (int)sizeof(float));

    /* per-launch prep */
    prep_aadj<<<(K_N * V_N * 28 + 255) / 256, 256>>>(A, emul, eadd);
    transpose_h<<<N_BATCH, 256>>>(hidden, pHA);
    cudaMemcpyAsync(pWhcat,              Whr, 256 * 256 * sizeof(float),
                    cudaMemcpyDeviceToDevice, 0);
    cudaMemcpyAsync(pWhcat + 256 * 256,  Whi, 256 * 256 * sizeof(float),
                    cudaMemcpyDeviceToDevice, 0);
    cudaMemcpyAsync(pWhcat + 2 * 256 * 256, Whh, 256 * 256 * sizeof(float),
                    cudaMemcpyDeviceToDevice, 0);
    cudaMemcpyAsync(Pbuf[0], in0, (size_t)NV * 3 * sizeof(float),
                    cudaMemcpyDeviceToDevice, 0);
    cudaMemcpyAsync(Pbuf[1], in1, (size_t)NV * 3 * sizeof(float),
                    cudaMemcpyDeviceToDevice, 0);
    cudaMemcpyAsync(Pbuf[2], in2, (size_t)NV * 3 * sizeof(float),
                    cudaMemcpyDeviceToDevice, 0);

    const dim3 grid768(6, NV / 128);   /* 768-wide GEMMs */
    const dim3 grid256(2, NV / 128);   /* 256-wide GEMMs */

    for (int s = 0; s < TS; s++) {
        float* Hcur  = (s & 1) ? pHB : pHA;
        float* Hnext = (s & 1) ? pHA : pHB;
        const float* Min = Hcur;

        if (s < 10) {
            sgemm_nt_128<<<grid768, 256>>>(Hcur, conv_w, pY, 768, conv_b, 1);
            graphmix_kernel<<<N_BATCH, 256, V_N * 768 * sizeof(float)>>>(pY, pM);
            Min = pM;
        }

        sgemm_nt_128<<<grid768, 256>>>(Min, pWhcat, pG, 768, nullptr, 0);

        int m4 = s & 3;
        int i1   = (4 - m4) & 3;
        int i2   = (5 - m4) & 3;
        int i3   = (6 - m4) & 3;
        int inew = (7 - m4) & 3;

        gru_kernel<<<NV, 256>>>(Hcur, pG, Pbuf[i1], Pbuf[i2], Pbuf[i3],
                                Wir, bir, Wii, bii, Win, b_in, Hnext, s);

        sgemm_nt_128<<<grid256, 256>>>(Hnext, W1, pD1, 256, b1, 2);
        sgemm_nt_128<<<grid256, 256>>>(pD1,  W2, pD2, 256, b2, 2);

        out_kernel<<<NV / 8, 256>>>(pD2, W3, b3, Pbuf[i1], Pbuf[inew], out, s);
    }
}

// round 7
// speedup vs baseline: 1.7679x; 1.7679x over previous
#include <cuda_runtime.h>
#include <cuda_bf16.h>
#include <math.h>
#include <stdint.h>

#define N_BATCH 4096
#define V_N     26
#define C_N     256
#define K_N     3
#define NV      (N_BATCH * V_N)            /* 106496 */
#define TS      25

/* ------------------------------------------------------------------ */
/* Device scratch (no cudaMalloc allowed)                              */
/* ------------------------------------------------------------------ */
__device__ float g_HA[(size_t)NV * C_N];        /* hidden fp32 ping    */
__device__ float g_HB[(size_t)NV * C_N];        /* hidden fp32 pong    */
__device__ float g_Y [(size_t)NV * 3 * C_N];    /* conv out fp32       */
__device__ float g_G [(size_t)NV * 3 * C_N];    /* gate pre-act fp32   */
__device__ float g_D2[(size_t)NV * C_N];
__device__ float g_P [4][(size_t)NV * 3];       /* pred history ring   */
__device__ __align__(16) float g_Aadj[K_N * V_N * 28];

/* bf16 hi/lo split activation buffers */
__device__ __nv_bfloat16 g_HAh[(size_t)NV * C_N], g_HAl[(size_t)NV * C_N];
__device__ __nv_bfloat16 g_HBh[(size_t)NV * C_N], g_HBl[(size_t)NV * C_N];
__device__ __nv_bfloat16 g_Mh [(size_t)NV * C_N], g_Ml [(size_t)NV * C_N];
__device__ __nv_bfloat16 g_D1h[(size_t)NV * C_N], g_D1l[(size_t)NV * C_N];

/* bf16 hi/lo split weights */
__device__ __nv_bfloat16 g_cwH[768 * 256], g_cwL[768 * 256];
__device__ __nv_bfloat16 g_WhH[768 * 256], g_WhL[768 * 256];
__device__ __nv_bfloat16 g_W1H[256 * 256], g_W1L[256 * 256];
__device__ __nv_bfloat16 g_W2H[256 * 256], g_W2L[256 * 256];

/* ------------------------------------------------------------------ */
/* JAX threefry2x32 noise (partitionable path; verified R4)            */
/* ------------------------------------------------------------------ */
__device__ __forceinline__ uint32_t rotl32(uint32_t x, uint32_t r) {
    return (x << r) | (x >> (32u - r));
}

__device__ __forceinline__ float jax_noise(int s, int r, int d)
{
    uint32_t idx = (uint32_t)((s * NV + r) * 3 + d);
    uint32_t x0 = 0u, x1 = idx;
    const uint32_t K0 = 0u, K1 = 1u, K2 = 0x1BD11BDBu;
    x0 += K0; x1 += K1;
#define QR(rv) { x0 += x1; x1 = rotl32(x1, rv); x1 ^= x0; }
    QR(13) QR(15) QR(26) QR(6)
    x0 += K1; x1 += K2 + 1u;
    QR(17) QR(29) QR(16) QR(24)
    x0 += K2; x1 += K0 + 2u;
    QR(13) QR(15) QR(26) QR(6)
    x0 += K0; x1 += K1 + 3u;
    QR(17) QR(29) QR(16) QR(24)
    x0 += K1; x1 += K2 + 4u;
    QR(13) QR(15) QR(26) QR(6)
    x0 += K2; x1 += K0 + 5u;
#undef QR
    uint32_t bits = x0 ^ x1;
    float f = __uint_as_float((bits >> 9) | 0x3f800000u) - 1.0f;
    const float lo = -0.99999994f;
    float u = fmaxf(lo, f * 2.0f + lo);
    return (1.41421354f * erfinvf(u)) * 5e-4f;
}

/* ------------------------------------------------------------------ */
/* helpers                                                             */
/* ------------------------------------------------------------------ */
__device__ __forceinline__ uint32_t smem_u32(const void* p) {
    uint32_t a;
    asm("{ .reg .u64 t; cvta.to.shared.u64 t, %1; cvt.u32.u64 %0, t; }"
        : "=r"(a) : "l"(p));
    return a;
}

__device__ __forceinline__ void ldsm4(uint32_t* d, uint32_t addr) {
    asm volatile("ldmatrix.sync.aligned.m8n8.x4.shared.b16 {%0,%1,%2,%3}, [%4];"
                 : "=r"(d[0]), "=r"(d[1]), "=r"(d[2]), "=r"(d[3]) : "r"(addr));
}

__device__ __forceinline__ void mma_bf16(float* c, const uint32_t* a, const uint32_t* b) {
    asm volatile("mma.sync.aligned.m16n8k16.row.col.f32.bf16.bf16.f32 "
                 "{%0,%1,%2,%3}, {%4,%5,%6,%7}, {%8,%9}, {%0,%1,%2,%3};"
                 : "+f"(c[0]), "+f"(c[1]), "+f"(c[2]), "+f"(c[3])
                 : "r"(a[0]), "r"(a[1]), "r"(a[2]), "r"(a[3]),
                   "r"(b[0]), "r"(b[1]));
}

__device__ __forceinline__ void split1(float x, __nv_bfloat16& h, __nv_bfloat16& l) {
    h = __float2bfloat16(x);
    l = __float2bfloat16(x - __bfloat162float(h));
}

/* ------------------------------------------------------------------ */
/* GEMM via mma.sync bf16-split:                                       */
/* C[M,Nout] = (Ah+Al)[M,256] @ (Bh+Bl)[Nout,256]^T  (3-product)       */
/* grid (Nout/128, M/128), 256 thr, 8 warps 4m x 2n, warp tile 32x64.  */
/* epi: 0 none, 1 +bias, 2 +bias+leaky(0.1).                           */
/* Cf (fp32) and/or Ch/Cl (split bf16) outputs, either may be null.    */
/* ------------------------------------------------------------------ */
#define STRB 72                               /* smem row stride (bf16) */
#define GEMM_SMEM (4 * 128 * STRB * 2)        /* 73728 bytes            */

__global__ void __launch_bounds__(256)
gemm_mma(const __nv_bfloat16* __restrict__ Ah, const __nv_bfloat16* __restrict__ Al,
         const __nv_bfloat16* __restrict__ Bh, const __nv_bfloat16* __restrict__ Bl,
         float* __restrict__ Cf,
         __nv_bfloat16* __restrict__ Ch, __nv_bfloat16* __restrict__ Cl,
         int Nout, const float* __restrict__ bias, int epi)
{
    extern __shared__ __align__(16) char sm[];
    const uint32_t sb  = smem_u32(sm);
    const uint32_t aAh = sb;
    const uint32_t aAl = sb + 128 * STRB * 2;
    const uint32_t aBh = sb + 2 * 128 * STRB * 2;
    const uint32_t aBl = sb + 3 * 128 * STRB * 2;
    __nv_bfloat16* sAh = (__nv_bfloat16*)sm;
    __nv_bfloat16* sAl = sAh + 128 * STRB;
    __nv_bfloat16* sBh = sAl + 128 * STRB;
    __nv_bfloat16* sBl = sBh + 128 * STRB;

    const int tid  = threadIdx.x;
    const int lane = tid & 31, w = tid >> 5;
    const int wm = w >> 1, wn = w & 1;
    const int m0 = blockIdx.y * 128, n0 = blockIdx.x * 128;

    float acc[2][8][4];
#pragma unroll
    for (int i = 0; i < 2; i++)
#pragma unroll
        for (int j = 0; j < 8; j++)
#pragma unroll
            for (int q = 0; q < 4; q++) acc[i][j][q] = 0.f;

    const int lrow = tid >> 1;
    const int lcol = (tid & 1) * 32;

    for (int kc = 0; kc < 4; kc++) {
        const int kb = kc * 64;
        const uint4* gAh = (const uint4*)(Ah + (size_t)(m0 + lrow) * 256 + kb + lcol);
        const uint4* gAl = (const uint4*)(Al + (size_t)(m0 + lrow) * 256 + kb + lcol);
        const uint4* gBh = (const uint4*)(Bh + (size_t)(n0 + lrow) * 256 + kb + lcol);
        const uint4* gBl = (const uint4*)(Bl + (size_t)(n0 + lrow) * 256 + kb + lcol);
        uint4* dAh = (uint4*)(sAh + lrow * STRB + lcol);
        uint4* dAl = (uint4*)(sAl + lrow * STRB + lcol);
        uint4* dBh = (uint4*)(sBh + lrow * STRB + lcol);
        uint4* dBl = (uint4*)(sBl + lrow * STRB + lcol);
        __syncthreads();
#pragma unroll
        for (int i = 0; i < 4; i++) {
            dAh[i] = gAh[i];
            dAl[i] = gAl[i];
            dBh[i] = gBh[i];
            dBl[i] = gBl[i];
        }
        __syncthreads();

#pragma unroll
        for (int ks = 0; ks < 4; ks++) {
            uint32_t ah[2][4], alr[2][4];
#pragma unroll
            for (int mt = 0; mt < 2; mt++) {
                uint32_t r = (uint32_t)(wm * 32 + mt * 16 + (lane & 15));
                uint32_t c = (uint32_t)(ks * 16 + (lane >> 4) * 8);
                uint32_t off = (r * STRB + c) * 2;
                ldsm4(ah[mt],  aAh + off);
                ldsm4(alr[mt], aAl + off);
            }
#pragma unroll
            for (int p = 0; p < 4; p++) {
                uint32_t bh[4], bl[4];
                uint32_t g = lane >> 3, rr = lane & 7;
                uint32_t r = (uint32_t)(wn * 64 + p * 16 + ((g & 2) ? 8 : 0) + rr);
                uint32_t c = (uint32_t)(ks * 16 + ((g & 1) ? 8 : 0));
                uint32_t off = (r * STRB + c) * 2;
                ldsm4(bh, aBh + off);
                ldsm4(bl, aBl + off);
#pragma unroll
                for (int mt = 0; mt < 2; mt++)
#pragma unroll
                    for (int q = 0; q < 2; q++) {
                        float* cc = acc[mt][p * 2 + q];
                        mma_bf16(cc, ah[mt],  &bh[q * 2]);
                        mma_bf16(cc, ah[mt],  &bl[q * 2]);
                        mma_bf16(cc, alr[mt], &bh[q * 2]);
                    }
            }
        }
    }

    /* epilogue */
#pragma unroll
    for (int mt = 0; mt < 2; mt++) {
        const int r0 = m0 + wm * 32 + mt * 16 + (lane >> 2);
#pragma unroll
        for (int nt = 0; nt < 8; nt++) {
            const int c0 = n0 + wn * 64 + nt * 8 + (lane & 3) * 2;
            float b0 = 0.f, b1 = 0.f;
            if (bias) { b0 = bias[c0]; b1 = bias[c0 + 1]; }
#pragma unroll
            for (int h = 0; h < 2; h++) {
                const int r = r0 + h * 8;
                float v0 = acc[mt][nt][h * 2 + 0] + b0;
                float v1 = acc[mt][nt][h * 2 + 1] + b1;
                if (epi == 2) {
                    v0 = v0 > 0.f ? v0 : 0.1f * v0;
                    v1 = v1 > 0.f ? v1 : 0.1f * v1;
                }
                const size_t o = (size_t)r * Nout + c0;
                if (Cf) *(float2*)(Cf + o) = make_float2(v0, v1);
                if (Ch) {
                    __nv_bfloat16 h0, l0, h1, l1;
                    split1(v0, h0, l0);
                    split1(v1, h1, l1);
                    *(uint32_t*)(Ch + o) =
                        ((uint32_t)__bfloat16_as_ushort(h1) << 16) | __bfloat16_as_ushort(h0);
                    *(uint32_t*)(Cl + o) =
                        ((uint32_t)__bfloat16_as_ushort(l1) << 16) | __bfloat16_as_ushort(l0);
                }
            }
        }
    }
}

/* ------------------------------------------------------------------ */
/* Graph mix: M[(n,w),c] = sum_{k,v} Y[(n,v),k*256+c] * Aadj[k,v,w]    */
/* writes split bf16 only (consumed solely as GEMM A-operand)          */
/* ------------------------------------------------------------------ */
__global__ void __launch_bounds__(256)
graphmix_kernel(const float* __restrict__ Y,
                __nv_bfloat16* __restrict__ Mh, __nv_bfloat16* __restrict__ Ml)
{
    extern __shared__ float smY[];                 /* 26*768 floats */
    __shared__ __align__(16) float sA[K_N * V_N * 28];
    const int n = blockIdx.x;
    const int tid = threadIdx.x;
    const float* Yn = Y + (size_t)n * V_N * 768;
    for (int i = tid; i < V_N * 768; i += 256) smY[i] = Yn[i];
    for (int i = tid; i < K_N * V_N * 28; i += 256) sA[i] = g_Aadj[i];
    __syncthreads();

    const int c = tid;
    float acc[28];
#pragma unroll
    for (int w = 0; w < 28; w++) acc[w] = 0.f;

#pragma unroll
    for (int k = 0; k < K_N; k++) {
#pragma unroll
        for (int v = 0; v < V_N; v++) {
            float yv = smY[v * 768 + k * 256 + c];
            const float4* arow = (const float4*)&sA[(k * V_N + v) * 28];
#pragma unroll
            for (int q = 0; q < 7; q++) {
                float4 a4 = arow[q];
                acc[q * 4 + 0] += yv * a4.x;
                acc[q * 4 + 1] += yv * a4.y;
                acc[q * 4 + 2] += yv * a4.z;
                acc[q * 4 + 3] += yv * a4.w;
            }
        }
    }
    for (int w = 0; w < V_N; w++) {
        __nv_bfloat16 h, l;
        split1(acc[w], h, l);
        const size_t o = ((size_t)n * V_N + w) * 256 + c;
        Mh[o] = h;
        Ml[o] = l;
    }
}

/* ------------------------------------------------------------------ */
/* GRU elementwise; writes Hnew fp32 + split bf16                      */
/* ------------------------------------------------------------------ */
__global__ void __launch_bounds__(256)
gru_kernel(const float* __restrict__ H, const float* __restrict__ G,
           const float* __restrict__ P1, const float* __restrict__ P2,
           const float* __restrict__ P3,
           const float* __restrict__ Wir, const float* __restrict__ bir,
           const float* __restrict__ Wii, const float* __restrict__ bii,
           const float* __restrict__ Win, const float* __restrict__ bin,
           float* __restrict__ Hnew,
           __nv_bfloat16* __restrict__ Hh, __nv_bfloat16* __restrict__ Hl,
           int s)
{
    const int r = blockIdx.x;
    const int c = threadIdx.x;
    __shared__ float sx[9];
    if (c < 3) {
        float h1 = P1[r * 3 + c], h2 = P2[r * 3 + c], h3 = P3[r * 3 + c];
        float nz = jax_noise(s, r, c);
        float insv = h2 - h3;
        sx[c]     = h1 + nz;
        sx[3 + c] = insv;
        sx[6 + c] = (h1 - h2) - insv;
    }
    __syncthreads();

    float xr = bir[c], xi = bii[c], xn = bin[c];
#pragma unroll
    for (int d = 0; d < 9; d++) {
        float xv = sx[d];
        xr += xv * Wir[c * 9 + d];
        xi += xv * Wii[c * 9 + d];
        xn += xv * Win[c * 9 + d];
    }
    size_t g = (size_t)r * 768;
    float gr = G[g + c], gi = G[g + 256 + c], gh = G[g + 512 + c];
    float rg = 1.f / (1.f + expf(-(xr + gr)));
    float zg = 1.f / (1.f + expf(-(xi + gi)));
    float nn = tanhf(xn + rg * gh);
    float hp = H[(size_t)r * 256 + c];
    float hv = (1.f - zg) * nn + zg * hp;
    const size_t o = (size_t)r * 256 + c;
    Hnew[o] = hv;
    __nv_bfloat16 hh, hl;
    split1(hv, hh, hl);
    Hh[o] = hh;
    Hl[o] = hl;
}

/* ------------------------------------------------------------------ */
/* Output head                                                         */
/* ------------------------------------------------------------------ */
__global__ void __launch_bounds__(256)
out_kernel(const float* __restrict__ D2, const float* __restrict__ W3,
           const float* __restrict__ b3, const float* __restrict__ P1,
           float* __restrict__ Pnew, float* __restrict__ out, int s)
{
    const int warp = threadIdx.x >> 5, lane = threadIdx.x & 31;
    const int r = blockIdx.x * 8 + warp;
    const float* row = D2 + (size_t)r * 256;
    float a0 = 0.f, a1 = 0.f, a2 = 0.f;
#pragma unroll
    for (int i = 0; i < 8; i++) {
        int c = lane + 32 * i;
        float v = row[c];
        a0 += v * W3[c];
        a1 += v * W3[256 + c];
        a2 += v * W3[512 + c];
    }
#pragma unroll
    for (int o = 16; o > 0; o >>= 1) {
        a0 += __shfl_down_sync(0xffffffffu, a0, o);
        a1 += __shfl_down_sync(0xffffffffu, a1, o);
        a2 += __shfl_down_sync(0xffffffffu, a2, o);
    }
    if (lane == 0) {
        float res[3] = {a0 + b3[0], a1 + b3[1], a2 + b3[2]};
#pragma unroll
        for (int d = 0; d < 3; d++) {
            float p = (P1[r * 3 + d] + jax_noise(s, r, d)) + res[d];
            Pnew[r * 3 + d] = p;
            out[((size_t)r * TS + s) * 3 + d] = p;
        }
    }
}

/* ------------------------------------------------------------------ */
/* Prep kernels                                                        */
/* ------------------------------------------------------------------ */
__global__ void prep_aadj(const float* __restrict__ A,
                          const float* __restrict__ em,
                          const float* __restrict__ ea)
{
    int i = blockIdx.x * 256 + threadIdx.x;
    if (i >= K_N * V_N * 28) return;
    int w = i % 28, kv = i / 28;
    g_Aadj[i] = (w < V_N) ? (A[kv * V_N + w] * em[kv * V_N + w] + ea[kv * V_N + w])
                          : 0.f;
}

__global__ void split_arr(const float* __restrict__ src,
                          __nv_bfloat16* __restrict__ h,
                          __nv_bfloat16* __restrict__ l, int n)
{
    int i = blockIdx.x * 256 + threadIdx.x;
    if (i < n) {
        __nv_bfloat16 hh, ll;
        split1(src[i], hh, ll);
        h[i] = hh;
        l[i] = ll;
    }
}

/* hidden [N,C,V] -> H [(n,v),c] fp32 + split, one block per n */
__global__ void __launch_bounds__(256)
transpose_h(const float* __restrict__ hid, float* __restrict__ H,
            __nv_bfloat16* __restrict__ Hh, __nv_bfloat16* __restrict__ Hl)
{
    __shared__ float sm[C_N * V_N];
    const int n = blockIdx.x;
    const float* src = hid + (size_t)n * C_N * V_N;
    for (int i = threadIdx.x; i < C_N * V_N; i += 256) sm[i] = src[i];
    __syncthreads();
    const size_t base = (size_t)n * V_N * C_N;
    for (int i = threadIdx.x; i < C_N * V_N; i += 256) {
        int v = i >> 8, c = i & 255;
        float x = sm[c * V_N + v];
        H[base + i] = x;
        __nv_bfloat16 hh, ll;
        split1(x, hh, ll);
        Hh[base + i] = hh;
        Hl[base + i] = ll;
    }
}

/* ------------------------------------------------------------------ */
/* Host driver                                                         */
/* ------------------------------------------------------------------ */
extern "C" void kernel_launch(void* const* d_in, const int* in_sizes, int n_in,
                              void* d_out, int out_size)
{
    const float* in0    = (const float*)d_in[0];
    const float* in1    = (const float*)d_in[1];
    const float* in2    = (const float*)d_in[2];
    const float* hidden = (const float*)d_in[3];
    const float* A      = (const float*)d_in[4];
    const float* emul   = (const float*)d_in[5];
    const float* eadd   = (const float*)d_in[6];
    const float* conv_w = (const float*)d_in[7];
    const float* conv_b = (const float*)d_in[8];
    const float* Wir    = (const float*)d_in[9];
    const float* bir    = (const float*)d_in[10];
    const float* Wii    = (const float*)d_in[11];
    const float* bii    = (const float*)d_in[12];
    const float* Win    = (const float*)d_in[13];
    const float* b_in   = (const float*)d_in[14];
    const float* Whr    = (const float*)d_in[15];
    const float* Whi    = (const float*)d_in[16];
    const float* Whh    = (const float*)d_in[17];
    const float* W1     = (const float*)d_in[18];
    const float* b1     = (const float*)d_in[19];
    const float* W2     = (const float*)d_in[20];
    const float* b2     = (const float*)d_in[21];
    const float* W3     = (const float*)d_in[22];
    const float* b3     = (const float*)d_in[23];
    float* out = (float*)d_out;

    float *pHA, *pHB, *pY, *pG, *pD2, *pPbase;
    cudaGetSymbolAddress((void**)&pHA, g_HA);
    cudaGetSymbolAddress((void**)&pHB, g_HB);
    cudaGetSymbolAddress((void**)&pY,  g_Y);
    cudaGetSymbolAddress((void**)&pG,  g_G);
    cudaGetSymbolAddress((void**)&pD2, g_D2);
    cudaGetSymbolAddress((void**)&pPbase, g_P);

    __nv_bfloat16 *pHAh, *pHAl, *pHBh, *pHBl, *pMh, *pMl, *pD1h, *pD1l;
    __nv_bfloat16 *pcwH, *pcwL, *pWhH, *pWhL, *pW1H, *pW1L, *pW2H, *pW2L;
    cudaGetSymbolAddress((void**)&pHAh, g_HAh);
    cudaGetSymbolAddress((void**)&pHAl, g_HAl);
    cudaGetSymbolAddress((void**)&pHBh, g_HBh);
    cudaGetSymbolAddress((void**)&pHBl, g_HBl);
    cudaGetSymbolAddress((void**)&pMh,  g_Mh);
    cudaGetSymbolAddress((void**)&pMl,  g_Ml);
    cudaGetSymbolAddress((void**)&pD1h, g_D1h);
    cudaGetSymbolAddress((void**)&pD1l, g_D1l);
    cudaGetSymbolAddress((void**)&pcwH, g_cwH);
    cudaGetSymbolAddress((void**)&pcwL, g_cwL);
    cudaGetSymbolAddress((void**)&pWhH, g_WhH);
    cudaGetSymbolAddress((void**)&pWhL, g_WhL);
    cudaGetSymbolAddress((void**)&pW1H, g_W1H);
    cudaGetSymbolAddress((void**)&pW1L, g_W1L);
    cudaGetSymbolAddress((void**)&pW2H, g_W2H);
    cudaGetSymbolAddress((void**)&pW2L, g_W2L);

    float* Pbuf[4];
    for (int i = 0; i < 4; i++) Pbuf[i] = pPbase + (size_t)i * NV * 3;

    cudaFuncSetAttribute(graphmix_kernel,
                         cudaFuncAttributeMaxDynamicSharedMemorySize,
                         V_N * 768 * (int)sizeof(float));
    cudaFuncSetAttribute(gemm_mma,
                         cudaFuncAttributeMaxDynamicSharedMemorySize,
                         GEMM_SMEM);

    /* per-launch prep */
    prep_aadj<<<(K_N * V_N * 28 + 255) / 256, 256>>>(A, emul, eadd);
    transpose_h<<<N_BATCH, 256>>>(hidden, pHA, pHAh, pHAl);
    split_arr<<<(768 * 256 + 255) / 256, 256>>>(conv_w, pcwH, pcwL, 768 * 256);
    split_arr<<<(256 * 256 + 255) / 256, 256>>>(Whr, pWhH,               pWhL,               256 * 256);
    split_arr<<<(256 * 256 + 255) / 256, 256>>>(Whi, pWhH + 256 * 256,   pWhL + 256 * 256,   256 * 256);
    split_arr<<<(256 * 256 + 255) / 256, 256>>>(Whh, pWhH + 512 * 256,   pWhL + 512 * 256,   256 * 256);
    split_arr<<<(256 * 256 + 255) / 256, 256>>>(W1, pW1H, pW1L, 256 * 256);
    split_arr<<<(256 * 256 + 255) / 256, 256>>>(W2, pW2H, pW2L, 256 * 256);
    cudaMemcpyAsync(Pbuf[0], in0, (size_t)NV * 3 * sizeof(float),
                    cudaMemcpyDeviceToDevice, 0);
    cudaMemcpyAsync(Pbuf[1], in1, (size_t)NV * 3 * sizeof(float),
                    cudaMemcpyDeviceToDevice, 0);
    cudaMemcpyAsync(Pbuf[2], in2, (size_t)NV * 3 * sizeof(float),
                    cudaMemcpyDeviceToDevice, 0);

    const dim3 grid768(6, NV / 128);
    const dim3 grid256(2, NV / 128);

    for (int s = 0; s < TS; s++) {
        float* Hcur  = (s & 1) ? pHB : pHA;
        float* Hnext = (s & 1) ? pHA : pHB;
        const __nv_bfloat16* Hch = (s & 1) ? pHBh : pHAh;
        const __nv_bfloat16* Hcl = (s & 1) ? pHBl : pHAl;
        __nv_bfloat16* Hnh = (s & 1) ? pHAh : pHBh;
        __nv_bfloat16* Hnl = (s & 1) ? pHAl : pHBl;

        const __nv_bfloat16 *GAh = Hch, *GAl = Hcl;
        if (s < 10) {
            gemm_mma<<<grid768, 256, GEMM_SMEM>>>(Hch, Hcl, pcwH, pcwL,
                                                  pY, nullptr, nullptr,
                                                  768, conv_b, 1);
            graphmix_kernel<<<N_BATCH, 256, V_N * 768 * sizeof(float)>>>(pY, pMh, pMl);
            GAh = pMh;
            GAl = pMl;
        }

        gemm_mma<<<grid768, 256, GEMM_SMEM>>>(GAh, GAl, pWhH, pWhL,
                                              pG, nullptr, nullptr,
                                              768, nullptr, 0);

        int m4 = s & 3;
        int i1   = (4 - m4) & 3;
        int i2   = (5 - m4) & 3;
        int i3   = (6 - m4) & 3;
        int inew = (7 - m4) & 3;

        gru_kernel<<<NV, 256>>>(Hcur, pG, Pbuf[i1], Pbuf[i2], Pbuf[i3],
                                Wir, bir, Wii, bii, Win, b_in,
                                Hnext, Hnh, Hnl, s);

        gemm_mma<<<grid256, 256, GEMM_SMEM>>>(Hnh, Hnl, pW1H, pW1L,
                                              nullptr, pD1h, pD1l,
                                              256, b1, 2);
        gemm_mma<<<grid256, 256, GEMM_SMEM>>>(pD1h, pD1l, pW2H, pW2L,
                                              pD2, nullptr, nullptr,
                                              256, b2, 2);

        out_kernel<<<NV / 8, 256>>>(pD2, W3, b3, Pbuf[i1], Pbuf[inew], out, s);
    }
}

// round 8
// speedup vs baseline: 2.2338x; 1.2635x over previous
#include <cuda_runtime.h>
#include <cuda_bf16.h>
#include <math.h>
#include <stdint.h>

#define N_BATCH 4096
#define V_N     26
#define C_N     256
#define K_N     3
#define NV      (N_BATCH * V_N)            /* 106496 */
#define TS      25

/* ------------------------------------------------------------------ */
/* Device scratch (no cudaMalloc allowed)                              */
/* ------------------------------------------------------------------ */
__device__ float g_HA[(size_t)NV * C_N];        /* hidden fp32 ping    */
__device__ float g_HB[(size_t)NV * C_N];        /* hidden fp32 pong    */
__device__ float g_Y [(size_t)NV * 3 * C_N];    /* conv out fp32       */
__device__ float g_G [(size_t)NV * 3 * C_N];    /* gate pre-act fp32   */
__device__ float g_D2[(size_t)NV * C_N];
__device__ float g_P [4][(size_t)NV * 3];       /* pred history ring   */
__device__ __align__(16) float g_Aadj[K_N * V_N * 28];

/* bf16 hi/lo split activation buffers */
__device__ __nv_bfloat16 g_HAh[(size_t)NV * C_N], g_HAl[(size_t)NV * C_N];
__device__ __nv_bfloat16 g_HBh[(size_t)NV * C_N], g_HBl[(size_t)NV * C_N];
__device__ __nv_bfloat16 g_Mh [(size_t)NV * C_N], g_Ml [(size_t)NV * C_N];
__device__ __nv_bfloat16 g_D1h[(size_t)NV * C_N], g_D1l[(size_t)NV * C_N];

/* bf16 hi/lo split weights */
__device__ __nv_bfloat16 g_cwH[768 * 256], g_cwL[768 * 256];
__device__ __nv_bfloat16 g_WhH[768 * 256], g_WhL[768 * 256];
__device__ __nv_bfloat16 g_W1H[256 * 256], g_W1L[256 * 256];
__device__ __nv_bfloat16 g_W2H[256 * 256], g_W2L[256 * 256];

/* ------------------------------------------------------------------ */
/* JAX threefry2x32 noise (partitionable path; verified R4)            */
/* ------------------------------------------------------------------ */
__device__ __forceinline__ uint32_t rotl32(uint32_t x, uint32_t r) {
    return (x << r) | (x >> (32u - r));
}

__device__ __forceinline__ float jax_noise(int s, int r, int d)
{
    uint32_t idx = (uint32_t)((s * NV + r) * 3 + d);
    uint32_t x0 = 0u, x1 = idx;
    const uint32_t K0 = 0u, K1 = 1u, K2 = 0x1BD11BDBu;
    x0 += K0; x1 += K1;
#define QR(rv) { x0 += x1; x1 = rotl32(x1, rv); x1 ^= x0; }
    QR(13) QR(15) QR(26) QR(6)
    x0 += K1; x1 += K2 + 1u;
    QR(17) QR(29) QR(16) QR(24)
    x0 += K2; x1 += K0 + 2u;
    QR(13) QR(15) QR(26) QR(6)
    x0 += K0; x1 += K1 + 3u;
    QR(17) QR(29) QR(16) QR(24)
    x0 += K1; x1 += K2 + 4u;
    QR(13) QR(15) QR(26) QR(6)
    x0 += K2; x1 += K0 + 5u;
#undef QR
    uint32_t bits = x0 ^ x1;
    float f = __uint_as_float((bits >> 9) | 0x3f800000u) - 1.0f;
    const float lo = -0.99999994f;
    float u = fmaxf(lo, f * 2.0f + lo);
    return (1.41421354f * erfinvf(u)) * 5e-4f;
}

/* ------------------------------------------------------------------ */
/* helpers                                                             */
/* ------------------------------------------------------------------ */
__device__ __forceinline__ uint32_t smem_u32(const void* p) {
    uint32_t a;
    asm("{ .reg .u64 t; cvta.to.shared.u64 t, %1; cvt.u32.u64 %0, t; }"
        : "=r"(a) : "l"(p));
    return a;
}

__device__ __forceinline__ void ldsm4(uint32_t* d, uint32_t addr) {
    asm volatile("ldmatrix.sync.aligned.m8n8.x4.shared.b16 {%0,%1,%2,%3}, [%4];"
                 : "=r"(d[0]), "=r"(d[1]), "=r"(d[2]), "=r"(d[3]) : "r"(addr));
}

__device__ __forceinline__ void mma_bf16(float* c, const uint32_t* a, const uint32_t* b) {
    asm volatile("mma.sync.aligned.m16n8k16.row.col.f32.bf16.bf16.f32 "
                 "{%0,%1,%2,%3}, {%4,%5,%6,%7}, {%8,%9}, {%0,%1,%2,%3};"
                 : "+f"(c[0]), "+f"(c[1]), "+f"(c[2]), "+f"(c[3])
                 : "r"(a[0]), "r"(a[1]), "r"(a[2]), "r"(a[3]),
                   "r"(b[0]), "r"(b[1]));
}

#define CP16(dst, src) \
    asm volatile("cp.async.cg.shared.global [%0], [%1], 16;" \
                 :: "r"(dst), "l"(src) : "memory")
#define CP_COMMIT() asm volatile("cp.async.commit_group;" ::: "memory")
#define CP_WAIT(n)  asm volatile("cp.async.wait_group %0;" :: "n"(n) : "memory")

__device__ __forceinline__ void split1(float x, __nv_bfloat16& h, __nv_bfloat16& l) {
    h = __float2bfloat16(x);
    l = __float2bfloat16(x - __bfloat162float(h));
}

/* ------------------------------------------------------------------ */
/* GEMM via mma.sync bf16-split, cp.async double-buffered:             */
/* C[M,Nout] = (Ah+Al)[M,256] @ (Bh+Bl)[Nout,256]^T  (3-product)       */
/* grid (Nout/128, M/128), 256 thr, 8 warps 4m x 2n, warp tile 32x64.  */
/* BK=32, 2 stages. epi: 0 none, 1 +bias, 2 +bias+leaky(0.1).          */
/* ------------------------------------------------------------------ */
#define STR   40                              /* smem row stride (bf16) */
#define ARRB  (128 * STR * 2)                 /* bytes per tile: 10240  */
#define STAGEB (4 * ARRB)                     /* bytes per stage: 40960 */
#define GEMM_SMEM (2 * STAGEB)                /* 81920                  */

__global__ void __launch_bounds__(256)
gemm_mma(const __nv_bfloat16* __restrict__ Ah, const __nv_bfloat16* __restrict__ Al,
         const __nv_bfloat16* __restrict__ Bh, const __nv_bfloat16* __restrict__ Bl,
         float* __restrict__ Cf,
         __nv_bfloat16* __restrict__ Ch, __nv_bfloat16* __restrict__ Cl,
         int Nout, const float* __restrict__ bias, int epi)
{
    extern __shared__ __align__(16) char sm[];
    const uint32_t sb = smem_u32(sm);

    const int tid  = threadIdx.x;
    const int lane = tid & 31, w = tid >> 5;
    const int wm = w >> 1, wn = w & 1;
    const int m0 = blockIdx.y * 128, n0 = blockIdx.x * 128;

    float acc[2][8][4];
#pragma unroll
    for (int i = 0; i < 2; i++)
#pragma unroll
        for (int j = 0; j < 8; j++)
#pragma unroll
            for (int q = 0; q < 4; q++) acc[i][j][q] = 0.f;

    const int lrow = tid >> 1;
    const int lcol = (tid & 1) * 16;
    const size_t aoff = (size_t)(m0 + lrow) * 256 + lcol;
    const size_t boff = (size_t)(n0 + lrow) * 256 + lcol;
    const __nv_bfloat16* src[4] = { Ah + aoff, Al + aoff, Bh + boff, Bl + boff };
    const uint32_t dbase = sb + (uint32_t)(lrow * STR + lcol) * 2u;

    /* prefetch a BK=32 stage */
    auto load_stage = [&](int kc, int st) {
#pragma unroll
        for (int a = 0; a < 4; a++) {
            const __nv_bfloat16* s = src[a] + kc * 32;
            uint32_t d = dbase + st * STAGEB + a * ARRB;
            CP16(d,      s);
            CP16(d + 16, s + 8);
        }
        CP_COMMIT();
    };

    load_stage(0, 0);

    for (int kc = 0; kc < 8; kc++) {
        if (kc < 7) load_stage(kc + 1, (kc + 1) & 1);
        if (kc < 7) { CP_WAIT(1); } else { CP_WAIT(0); }
        __syncthreads();

        const uint32_t sbase = sb + (kc & 1) * STAGEB;
#pragma unroll
        for (int ks = 0; ks < 2; ks++) {
            uint32_t ah[2][4], alr[2][4];
#pragma unroll
            for (int mt = 0; mt < 2; mt++) {
                uint32_t r = (uint32_t)(wm * 32 + mt * 16 + (lane & 15));
                uint32_t c = (uint32_t)(ks * 16 + (lane >> 4) * 8);
                uint32_t off = sbase + (r * STR + c) * 2;
                ldsm4(ah[mt],  off);
                ldsm4(alr[mt], off + ARRB);
            }
#pragma unroll
            for (int p = 0; p < 4; p++) {
                uint32_t bh[4], bl[4];
                uint32_t g = lane >> 3, rr = lane & 7;
                uint32_t r = (uint32_t)(wn * 64 + p * 16 + ((g & 2) ? 8 : 0) + rr);
                uint32_t c = (uint32_t)(ks * 16 + ((g & 1) ? 8 : 0));
                uint32_t off = sbase + 2 * ARRB + (r * STR + c) * 2;
                ldsm4(bh, off);
                ldsm4(bl, off + ARRB);
#pragma unroll
                for (int mt = 0; mt < 2; mt++)
#pragma unroll
                    for (int q = 0; q < 2; q++) {
                        float* cc = acc[mt][p * 2 + q];
                        mma_bf16(cc, ah[mt],  &bh[q * 2]);
                        mma_bf16(cc, ah[mt],  &bl[q * 2]);
                        mma_bf16(cc, alr[mt], &bh[q * 2]);
                    }
            }
        }
        __syncthreads();
    }

    /* epilogue */
#pragma unroll
    for (int mt = 0; mt < 2; mt++) {
        const int r0 = m0 + wm * 32 + mt * 16 + (lane >> 2);
#pragma unroll
        for (int nt = 0; nt < 8; nt++) {
            const int c0 = n0 + wn * 64 + nt * 8 + (lane & 3) * 2;
            float b0 = 0.f, b1 = 0.f;
            if (bias) { b0 = bias[c0]; b1 = bias[c0 + 1]; }
#pragma unroll
            for (int h = 0; h < 2; h++) {
                const int r = r0 + h * 8;
                float v0 = acc[mt][nt][h * 2 + 0] + b0;
                float v1 = acc[mt][nt][h * 2 + 1] + b1;
                if (epi == 2) {
                    v0 = v0 > 0.f ? v0 : 0.1f * v0;
                    v1 = v1 > 0.f ? v1 : 0.1f * v1;
                }
                const size_t o = (size_t)r * Nout + c0;
                if (Cf) *(float2*)(Cf + o) = make_float2(v0, v1);
                if (Ch) {
                    __nv_bfloat16 h0, l0, h1, l1;
                    split1(v0, h0, l0);
                    split1(v1, h1, l1);
                    *(uint32_t*)(Ch + o) =
                        ((uint32_t)__bfloat16_as_ushort(h1) << 16) | __bfloat16_as_ushort(h0);
                    *(uint32_t*)(Cl + o) =
                        ((uint32_t)__bfloat16_as_ushort(l1) << 16) | __bfloat16_as_ushort(l0);
                }
            }
        }
    }
}

/* ------------------------------------------------------------------ */
/* Graph mix: M[(n,w),c] = sum_{k,v} Y[(n,v),k*256+c] * Aadj[k,v,w]    */
/* Y read direct from gmem (single-use, coalesced across c=tid).       */
/* ------------------------------------------------------------------ */
__global__ void __launch_bounds__(256)
graphmix_kernel(const float* __restrict__ Y,
                __nv_bfloat16* __restrict__ Mh, __nv_bfloat16* __restrict__ Ml)
{
    __shared__ __align__(16) float sA[K_N * V_N * 28];
    const int n = blockIdx.x;
    const int tid = threadIdx.x;
    for (int i = tid; i < K_N * V_N * 28; i += 256) sA[i] = g_Aadj[i];
    __syncthreads();

    const float* Yn = Y + (size_t)n * V_N * 768;
    const int c = tid;
    float acc[28];
#pragma unroll
    for (int w = 0; w < 28; w++) acc[w] = 0.f;

#pragma unroll
    for (int k = 0; k < K_N; k++) {
#pragma unroll
        for (int v = 0; v < V_N; v++) {
            float yv = Yn[v * 768 + k * 256 + c];
            const float4* arow = (const float4*)&sA[(k * V_N + v) * 28];
#pragma unroll
            for (int q = 0; q < 7; q++) {
                float4 a4 = arow[q];
                acc[q * 4 + 0] += yv * a4.x;
                acc[q * 4 + 1] += yv * a4.y;
                acc[q * 4 + 2] += yv * a4.z;
                acc[q * 4 + 3] += yv * a4.w;
            }
        }
    }
    for (int w = 0; w < V_N; w++) {
        __nv_bfloat16 h, l;
        split1(acc[w], h, l);
        const size_t o = ((size_t)n * V_N + w) * 256 + c;
        Mh[o] = h;
        Ml[o] = l;
    }
}

/* ------------------------------------------------------------------ */
/* GRU elementwise; writes Hnew fp32 + split bf16                      */
/* ------------------------------------------------------------------ */
__global__ void __launch_bounds__(256)
gru_kernel(const float* __restrict__ H, const float* __restrict__ G,
           const float* __restrict__ P1, const float* __restrict__ P2,
           const float* __restrict__ P3,
           const float* __restrict__ Wir, const float* __restrict__ bir,
           const float* __restrict__ Wii, const float* __restrict__ bii,
           const float* __restrict__ Win, const float* __restrict__ bin,
           float* __restrict__ Hnew,
           __nv_bfloat16* __restrict__ Hh, __nv_bfloat16* __restrict__ Hl,
           int s)
{
    const int r = blockIdx.x;
    const int c = threadIdx.x;
    __shared__ float sx[9];
    if (c < 3) {
        float h1 = P1[r * 3 + c], h2 = P2[r * 3 + c], h3 = P3[r * 3 + c];
        float nz = jax_noise(s, r, c);
        float insv = h2 - h3;
        sx[c]     = h1 + nz;
        sx[3 + c] = insv;
        sx[6 + c] = (h1 - h2) - insv;
    }
    __syncthreads();

    float xr = bir[c], xi = bii[c], xn = bin[c];
#pragma unroll
    for (int d = 0; d < 9; d++) {
        float xv = sx[d];
        xr += xv * Wir[c * 9 + d];
        xi += xv * Wii[c * 9 + d];
        xn += xv * Win[c * 9 + d];
    }
    size_t g = (size_t)r * 768;
    float gr = G[g + c], gi = G[g + 256 + c], gh = G[g + 512 + c];
    float rg = 1.f / (1.f + expf(-(xr + gr)));
    float zg = 1.f / (1.f + expf(-(xi + gi)));
    float nn = tanhf(xn + rg * gh);
    float hp = H[(size_t)r * 256 + c];
    float hv = (1.f - zg) * nn + zg * hp;
    const size_t o = (size_t)r * 256 + c;
    Hnew[o] = hv;
    __nv_bfloat16 hh, hl;
    split1(hv, hh, hl);
    Hh[o] = hh;
    Hl[o] = hl;
}

/* ------------------------------------------------------------------ */
/* Output head                                                         */
/* ------------------------------------------------------------------ */
__global__ void __launch_bounds__(256)
out_kernel(const float* __restrict__ D2, const float* __restrict__ W3,
           const float* __restrict__ b3, const float* __restrict__ P1,
           float* __restrict__ Pnew, float* __restrict__ out, int s)
{
    const int warp = threadIdx.x >> 5, lane = threadIdx.x & 31;
    const int r = blockIdx.x * 8 + warp;
    const float* row = D2 + (size_t)r * 256;
    float a0 = 0.f, a1 = 0.f, a2 = 0.f;
#pragma unroll
    for (int i = 0; i < 8; i++) {
        int c = lane + 32 * i;
        float v = row[c];
        a0 += v * W3[c];
        a1 += v * W3[256 + c];
        a2 += v * W3[512 + c];
    }
#pragma unroll
    for (int o = 16; o > 0; o >>= 1) {
        a0 += __shfl_down_sync(0xffffffffu, a0, o);
        a1 += __shfl_down_sync(0xffffffffu, a1, o);
        a2 += __shfl_down_sync(0xffffffffu, a2, o);
    }
    if (lane == 0) {
        float res[3] = {a0 + b3[0], a1 + b3[1], a2 + b3[2]};
#pragma unroll
        for (int d = 0; d < 3; d++) {
            float p = (P1[r * 3 + d] + jax_noise(s, r, d)) + res[d];
            Pnew[r * 3 + d] = p;
            out[((size_t)r * TS + s) * 3 + d] = p;
        }
    }
}

/* ------------------------------------------------------------------ */
/* Prep kernels                                                        */
/* ------------------------------------------------------------------ */
__global__ void prep_aadj(const float* __restrict__ A,
                          const float* __restrict__ em,
                          const float* __restrict__ ea)
{
    int i = blockIdx.x * 256 + threadIdx.x;
    if (i >= K_N * V_N * 28) return;
    int w = i % 28, kv = i / 28;
    g_Aadj[i] = (w < V_N) ? (A[kv * V_N + w] * em[kv * V_N + w] + ea[kv * V_N + w])
                          : 0.f;
}

__global__ void split_arr(const float* __restrict__ src,
                          __nv_bfloat16* __restrict__ h,
                          __nv_bfloat16* __restrict__ l, int n)
{
    int i = blockIdx.x * 256 + threadIdx.x;
    if (i < n) {
        __nv_bfloat16 hh, ll;
        split1(src[i], hh, ll);
        h[i] = hh;
        l[i] = ll;
    }
}

/* hidden [N,C,V] -> H [(n,v),c] fp32 + split, one block per n */
__global__ void __launch_bounds__(256)
transpose_h(const float* __restrict__ hid, float* __restrict__ H,
            __nv_bfloat16* __restrict__ Hh, __nv_bfloat16* __restrict__ Hl)
{
    __shared__ float sm[C_N * V_N];
    const int n = blockIdx.x;
    const float* src = hid + (size_t)n * C_N * V_N;
    for (int i = threadIdx.x; i < C_N * V_N; i += 256) sm[i] = src[i];
    __syncthreads();
    const size_t base = (size_t)n * V_N * C_N;
    for (int i = threadIdx.x; i < C_N * V_N; i += 256) {
        int v = i >> 8, c = i & 255;
        float x = sm[c * V_N + v];
        H[base + i] = x;
        __nv_bfloat16 hh, ll;
        split1(x, hh, ll);
        Hh[base + i] = hh;
        Hl[base + i] = ll;
    }
}

/* ------------------------------------------------------------------ */
/* Host driver                                                         */
/* ------------------------------------------------------------------ */
extern "C" void kernel_launch(void* const* d_in, const int* in_sizes, int n_in,
                              void* d_out, int out_size)
{
    const float* in0    = (const float*)d_in[0];
    const float* in1    = (const float*)d_in[1];
    const float* in2    = (const float*)d_in[2];
    const float* hidden = (const float*)d_in[3];
    const float* A      = (const float*)d_in[4];
    const float* emul   = (const float*)d_in[5];
    const float* eadd   = (const float*)d_in[6];
    const float* conv_w = (const float*)d_in[7];
    const float* conv_b = (const float*)d_in[8];
    const float* Wir    = (const float*)d_in[9];
    const float* bir    = (const float*)d_in[10];
    const float* Wii    = (const float*)d_in[11];
    const float* bii    = (const float*)d_in[12];
    const float* Win    = (const float*)d_in[13];
    const float* b_in   = (const float*)d_in[14];
    const float* Whr    = (const float*)d_in[15];
    const float* Whi    = (const float*)d_in[16];
    const float* Whh    = (const float*)d_in[17];
    const float* W1     = (const float*)d_in[18];
    const float* b1     = (const float*)d_in[19];
    const float* W2     = (const float*)d_in[20];
    const float* b2     = (const float*)d_in[21];
    const float* W3     = (const float*)d_in[22];
    const float* b3     = (const float*)d_in[23];
    float* out = (float*)d_out;

    float *pHA, *pHB, *pY, *pG, *pD2, *pPbase;
    cudaGetSymbolAddress((void**)&pHA, g_HA);
    cudaGetSymbolAddress((void**)&pHB, g_HB);
    cudaGetSymbolAddress((void**)&pY,  g_Y);
    cudaGetSymbolAddress((void**)&pG,  g_G);
    cudaGetSymbolAddress((void**)&pD2, g_D2);
    cudaGetSymbolAddress((void**)&pPbase, g_P);

    __nv_bfloat16 *pHAh, *pHAl, *pHBh, *pHBl, *pMh, *pMl, *pD1h, *pD1l;
    __nv_bfloat16 *pcwH, *pcwL, *pWhH, *pWhL, *pW1H, *pW1L, *pW2H, *pW2L;
    cudaGetSymbolAddress((void**)&pHAh, g_HAh);
    cudaGetSymbolAddress((void**)&pHAl, g_HAl);
    cudaGetSymbolAddress((void**)&pHBh, g_HBh);
    cudaGetSymbolAddress((void**)&pHBl, g_HBl);
    cudaGetSymbolAddress((void**)&pMh,  g_Mh);
    cudaGetSymbolAddress((void**)&pMl,  g_Ml);
    cudaGetSymbolAddress((void**)&pD1h, g_D1h);
    cudaGetSymbolAddress((void**)&pD1l, g_D1l);
    cudaGetSymbolAddress((void**)&pcwH, g_cwH);
    cudaGetSymbolAddress((void**)&pcwL, g_cwL);
    cudaGetSymbolAddress((void**)&pWhH, g_WhH);
    cudaGetSymbolAddress((void**)&pWhL, g_WhL);
    cudaGetSymbolAddress((void**)&pW1H, g_W1H);
    cudaGetSymbolAddress((void**)&pW1L, g_W1L);
    cudaGetSymbolAddress((void**)&pW2H, g_W2H);
    cudaGetSymbolAddress((void**)&pW2L, g_W2L);

    float* Pbuf[4];
    for (int i = 0; i < 4; i++) Pbuf[i] = pPbase + (size_t)i * NV * 3;

    cudaFuncSetAttribute(gemm_mma,
                         cudaFuncAttributeMaxDynamicSharedMemorySize,
                         GEMM_SMEM);

    /* per-launch prep */
    prep_aadj<<<(K_N * V_N * 28 + 255) / 256, 256>>>(A, emul, eadd);
    transpose_h<<<N_BATCH, 256>>>(hidden, pHA, pHAh, pHAl);
    split_arr<<<(768 * 256 + 255) / 256, 256>>>(conv_w, pcwH, pcwL, 768 * 256);
    split_arr<<<(256 * 256 + 255) / 256, 256>>>(Whr, pWhH,             pWhL,             256 * 256);
    split_arr<<<(256 * 256 + 255) / 256, 256>>>(Whi, pWhH + 256 * 256, pWhL + 256 * 256, 256 * 256);
    split_arr<<<(256 * 256 + 255) / 256, 256>>>(Whh, pWhH + 512 * 256, pWhL + 512 * 256, 256 * 256);
    split_arr<<<(256 * 256 + 255) / 256, 256>>>(W1, pW1H, pW1L, 256 * 256);
    split_arr<<<(256 * 256 + 255) / 256, 256>>>(W2, pW2H, pW2L, 256 * 256);
    cudaMemcpyAsync(Pbuf[0], in0, (size_t)NV * 3 * sizeof(float),
                    cudaMemcpyDeviceToDevice, 0);
    cudaMemcpyAsync(Pbuf[1], in1, (size_t)NV * 3 * sizeof(float),
                    cudaMemcpyDeviceToDevice, 0);
    cudaMemcpyAsync(Pbuf[2], in2, (size_t)NV * 3 * sizeof(float),
                    cudaMemcpyDeviceToDevice, 0);

    const dim3 grid768(6, NV / 128);
    const dim3 grid256(2, NV / 128);

    for (int s = 0; s < TS; s++) {
        float* Hcur  = (s & 1) ? pHB : pHA;
        float* Hnext = (s & 1) ? pHA : pHB;
        const __nv_bfloat16* Hch = (s & 1) ? pHBh : pHAh;
        const __nv_bfloat16* Hcl = (s & 1) ? pHBl : pHAl;
        __nv_bfloat16* Hnh = (s & 1) ? pHAh : pHBh;
        __nv_bfloat16* Hnl = (s & 1) ? pHAl : pHBl;

        const __nv_bfloat16 *GAh = Hch, *GAl = Hcl;
        if (s < 10) {
            gemm_mma<<<grid768, 256, GEMM_SMEM>>>(Hch, Hcl, pcwH, pcwL,
                                                  pY, nullptr, nullptr,
                                                  768, conv_b, 1);
            graphmix_kernel<<<N_BATCH, 256>>>(pY, pMh, pMl);
            GAh = pMh;
            GAl = pMl;
        }

        gemm_mma<<<grid768, 256, GEMM_SMEM>>>(GAh, GAl, pWhH, pWhL,
                                              pG, nullptr, nullptr,
                                              768, nullptr, 0);

        int m4 = s & 3;
        int i1   = (4 - m4) & 3;
        int i2   = (5 - m4) & 3;
        int i3   = (6 - m4) & 3;
        int inew = (7 - m4) & 3;

        gru_kernel<<<NV, 256>>>(Hcur, pG, Pbuf[i1], Pbuf[i2], Pbuf[i3],
                                Wir, bir, Wii, bii, Win, b_in,
                                Hnext, Hnh, Hnl, s);

        gemm_mma<<<grid256, 256, GEMM_SMEM>>>(Hnh, Hnl, pW1H, pW1L,
                                              nullptr, pD1h, pD1l,
                                              256, b1, 2);
        gemm_mma<<<grid256, 256, GEMM_SMEM>>>(pD1h, pD1l, pW2H, pW2L,
                                              pD2, nullptr, nullptr,
                                              256, b2, 2);

        out_kernel<<<NV / 8, 256>>>(pD2, W3, b3, Pbuf[i1], Pbuf[inew], out, s);
    }
}